// round 9
// baseline (speedup 1.0000x reference)
#include <cuda_runtime.h>
#include <cuda_bf16.h>
#include <stdint.h>

// ============================================================================
// DifferentialAttention — round 9: break MMA accumulator RAW chains
//
// Round-8 ncu (E-GEMM): tensor=46%, occ=23.3% (2 CTAs/SM achieved), DRAM 3.7%.
// Limiter: tn-major MMA order issued 3 back-to-back MMAs on the SAME
// accumulator (RAW chain depth 3 on ~16-32cy HMMA latency). Fix: term-major
// order within each tm -> dependent MMAs 4 slots apart, 4 independent chains
// per warp. Register-neutral, numerically bit-identical (per-accumulator
// hh->lh->hl order preserved).
//
//  out = diff @ x @ (Wv@Wo) + (1-lam)*(bv@Wo) + bo
//  diff = softmax(Q1K1^T/8) - lam*softmax(Q2K2^T/8); exp fused into logits
//  GEMM epilogue (no max-sub), normalization folded:
//  t = (1/S1) o (E1@x) - (lam/S2) o (E2@x)
// ============================================================================

#define SEQ 2048

// ---------------------------------------------------------------------------
// Scratch (device globals)
// ---------------------------------------------------------------------------
__device__ __align__(16) __nv_bfloat16 g_qkvh[4096 * 1024];
__device__ __align__(16) __nv_bfloat16 g_qkvl[4096 * 1024];
__device__ __align__(16) __nv_bfloat16 g_xh[4096 * 512];
__device__ __align__(16) __nv_bfloat16 g_xl[4096 * 512];
__device__ __align__(16) __nv_bfloat16 g_xTh[2 * 512 * 2048];
__device__ __align__(16) __nv_bfloat16 g_xTl[2 * 512 * 2048];
__device__ __align__(16) __nv_bfloat16 g_wqTh[1024 * 512];
__device__ __align__(16) __nv_bfloat16 g_wqTl[1024 * 512];
__device__ __align__(16) __nv_bfloat16 g_woTh[512 * 8192];
__device__ __align__(16) __nv_bfloat16 g_woTl[512 * 8192];
__device__ __align__(16) __nv_bfloat16 g_wvh[512 * 8192];
__device__ __align__(16) __nv_bfloat16 g_wvl[512 * 8192];
__device__ __align__(16) __nv_bfloat16 g_Eh[2LL * 2 * 2048 * 2048]; // [map][b][S][S]
__device__ __align__(16) __nv_bfloat16 g_El[2LL * 2 * 2048 * 2048];
__device__ float g_S[2 * 4096];                            // rowsums [map][b*S+r]
__device__ __align__(16) float g_u[2LL * 2 * 2048 * 512];  // [map][b][S][512]
__device__ __align__(16) __nv_bfloat16 g_th[4096 * 512];
__device__ __align__(16) __nv_bfloat16 g_tl[4096 * 512];
__device__ __align__(16) float g_W2p[8 * 512 * 512];
__device__ __align__(16) __nv_bfloat16 g_w2Th[512 * 512];
__device__ __align__(16) __nv_bfloat16 g_w2Tl[512 * 512];
__device__ float g_bfp[64 * 512];
__device__ float g_bfin[512];
__device__ float g_lam;

// ---------------------------------------------------------------------------
// PTX helpers (sm_80-era, valid on base sm_100)
// ---------------------------------------------------------------------------
__device__ __forceinline__ uint32_t smem_u32(const void* p) {
    uint32_t a;
    asm("{ .reg .u64 t; cvta.to.shared.u64 t, %1; cvt.u32.u64 %0, t; }"
        : "=r"(a) : "l"(p));
    return a;
}
__device__ __forceinline__ void cp16(uint32_t s, const void* g) {
    asm volatile("cp.async.cg.shared.global [%0], [%1], 16;" :: "r"(s), "l"(g));
}
#define CP_COMMIT() asm volatile("cp.async.commit_group;")
#define CP_WAIT(n)  asm volatile("cp.async.wait_group %0;" :: "n"(n))

__device__ __forceinline__ void ldsm_x4(uint32_t* r, uint32_t a) {
    asm volatile("ldmatrix.sync.aligned.m8n8.x4.shared.b16 {%0,%1,%2,%3}, [%4];"
                 : "=r"(r[0]), "=r"(r[1]), "=r"(r[2]), "=r"(r[3]) : "r"(a));
}
__device__ __forceinline__ void ldsm_x2(uint32_t* r, uint32_t a) {
    asm volatile("ldmatrix.sync.aligned.m8n8.x2.shared.b16 {%0,%1}, [%2];"
                 : "=r"(r[0]), "=r"(r[1]) : "r"(a));
}
__device__ __forceinline__ void mma16816(float* c, const uint32_t* a, const uint32_t* b) {
    asm volatile("mma.sync.aligned.m16n8k16.row.col.f32.bf16.bf16.f32 "
                 "{%0,%1,%2,%3}, {%4,%5,%6,%7}, {%8,%9}, {%0,%1,%2,%3};"
                 : "+f"(c[0]), "+f"(c[1]), "+f"(c[2]), "+f"(c[3])
                 : "r"(a[0]), "r"(a[1]), "r"(a[2]), "r"(a[3]), "r"(b[0]), "r"(b[1]));
}

// ---------------------------------------------------------------------------
// fast exp (FMA pipe, rel err ~2.4e-6)
// ---------------------------------------------------------------------------
__device__ __forceinline__ float fast_exp(float x) {
    x = fmaxf(x, -87.0f);
    float z  = x * 1.4426950408889634f;
    float nf = z + 12582912.0f;
    int   ei = __float_as_int(nf) - 0x4B400000;
    float f  = z - (nf - 12582912.0f);
    float p  =        1.3333558146e-3f;
    p = fmaf(p, f,    9.6181291e-3f);
    p = fmaf(p, f,    5.5504108664e-2f);
    p = fmaf(p, f,    2.4022650696e-1f);
    p = fmaf(p, f,    6.9314718056e-1f);
    p = fmaf(p, f,    1.0f);
    return __int_as_float(__float_as_int(p) + (ei << 23));
}
__device__ __forceinline__ uint32_t pack_bf2(__nv_bfloat16 a, __nv_bfloat16 b) {
    return (uint32_t)__bfloat16_as_ushort(a) | ((uint32_t)__bfloat16_as_ushort(b) << 16);
}

// ---------------------------------------------------------------------------
// HMMA GEMM: C = A @ B^T, A [M,K] hi/lo bf16 row-major, B [N,K] hi/lo.
// Block 128x128, K-chunk 32, 8 warps (2 M x 4 N), warp tile 64x32.
// 3-split per k16: Ah*Bh + Al*Bh + Ah*Bl (fp32 accum), issued term-major.
// MODE 0: C fp32.  MODE 1: + bias[n].  MODE 2: exp epilogue -> Hout/Lout bf16
// planes + atomicAdd rowsums.  MODE 3: (bias, scale cols<512 by 0.125) ->
// Hout/Lout bf16 planes; blockIdx.x==0 blocks also zero g_S.
// z decomposed as (z1, z2) = (z/zdiv, z%zdiv); offsets z1*s?1 + z2*s?2.
// Smem stage: 4 planes x (128 rows x 80B pitch) = 40960 B; 2 stages.
// 2 CTAs/SM (register-dieted mainloop + launch_bounds min-blocks 2).
// ---------------------------------------------------------------------------
#define PITCH 80
#define PLANE_BYTES (128 * PITCH)       // 10240
#define STAGE_BYTES (4 * PLANE_BYTES)   // 40960

template<int MODE>
__global__ void __launch_bounds__(256, 2)
hmma_gemm(const __nv_bfloat16* __restrict__ Ah, const __nv_bfloat16* __restrict__ Al,
          const __nv_bfloat16* __restrict__ Bh, const __nv_bfloat16* __restrict__ Bl,
          float* __restrict__ C, const float* __restrict__ bias,
          __nv_bfloat16* __restrict__ Hout, __nv_bfloat16* __restrict__ Lout,
          float* __restrict__ rowsum,
          int K, int lda, int ldb, int ldc, int zdiv,
          long long sA1, long long sA2, long long sB1, long long sB2,
          long long sC1, long long sC2, long long sR1, long long sR2)
{
    extern __shared__ __align__(16) char smem[];
    const uint32_t sb = smem_u32(smem);

    const int tid = threadIdx.x;
    const int lane = tid & 31, wid = tid >> 5;
    const int wm = wid & 1, wn = wid >> 1;
    const int m0 = blockIdx.y * 128, n0 = blockIdx.x * 128;
    const int z1 = blockIdx.z / zdiv, z2 = blockIdx.z % zdiv;
    const long long zA = z1 * sA1 + z2 * sA2;
    const long long zB = z1 * sB1 + z2 * sB2;
    const long long zC = z1 * sC1 + z2 * sC2;
    Ah += zA; Al += zA; Bh += zB; Bl += zB;

    if (MODE == 3 && blockIdx.x == 0) {
        // zero rowsum accumulators for the downstream E GEMM (8192 floats)
        g_S[blockIdx.y * 256 + tid] = 0.0f;
    }

    // loader: 64 threads per plane (0 Ahi, 1 Alo, 2 Bhi, 3 Blo)
    const int tsel = tid >> 6;
    const __nv_bfloat16* gbase =
        (tsel == 0) ? Ah : (tsel == 1) ? Al : (tsel == 2) ? Bh : Bl;
    const int row0 = (tsel < 2) ? m0 : n0;
    const int ld   = (tsel < 2) ? lda : ldb;
    const int r64  = tid & 63;
    const uint32_t plane_off = (uint32_t)tsel * PLANE_BYTES;

    const int nch = K >> 5;

#define LOAD_CHUNK(buf, k0) do { \
    uint32_t st_ = sb + (buf) * STAGE_BYTES + plane_off; \
    _Pragma("unroll") \
    for (int it_ = 0; it_ < 8; it_++) { \
        int idx_ = r64 + it_ * 64; \
        int row_ = idx_ >> 2, seg_ = idx_ & 3; \
        const __nv_bfloat16* g_ = gbase + (long long)(row0 + row_) * ld + (k0) + seg_ * 8; \
        cp16(st_ + row_ * PITCH + seg_ * 16, g_); \
    } \
    CP_COMMIT(); \
} while (0)

    LOAD_CHUNK(0, 0);

    float c[4][4][4];
#pragma unroll
    for (int a = 0; a < 4; a++)
#pragma unroll
        for (int b = 0; b < 4; b++)
#pragma unroll
            for (int q = 0; q < 4; q++) c[a][b][q] = 0.0f;

    for (int i = 0; i < nch; i++) {
        if (i + 1 < nch) {
            LOAD_CHUNK((i + 1) & 1, (i + 1) * 32);
            CP_WAIT(1);
        } else {
            CP_WAIT(0);
        }
        __syncthreads();

        const uint32_t stg = sb + (i & 1) * STAGE_BYTES;
        const uint32_t a_row_off = (uint32_t)(wm * 64 + (lane & 15)) * PITCH + (lane >> 4) * 16;
        const uint32_t b_row_off = (uint32_t)(wn * 32 + (lane & 7)) * PITCH + ((lane >> 3) & 1) * 16;

#pragma unroll
        for (int k16 = 0; k16 < 2; k16++) {
            const uint32_t ko = k16 * 32;
            // B fragments for this k16 (live: 16 regs)
            uint32_t bh[4][2], bl[4][2];
#pragma unroll
            for (int tn = 0; tn < 4; tn++) {
                ldsm_x2(bh[tn], stg + 2 * PLANE_BYTES + tn * 8 * PITCH + b_row_off + ko);
                ldsm_x2(bl[tn], stg + 3 * PLANE_BYTES + tn * 8 * PITCH + b_row_off + ko);
            }
            // A fragments per tm (live: 8 regs). Term-major MMA issue:
            // dependent MMAs on the same accumulator are 4 slots apart.
#pragma unroll
            for (int tm = 0; tm < 4; tm++) {
                uint32_t ah[4], al[4];
                ldsm_x4(ah, stg + 0 * PLANE_BYTES + tm * 16 * PITCH + a_row_off + ko);
                ldsm_x4(al, stg + 1 * PLANE_BYTES + tm * 16 * PITCH + a_row_off + ko);
#pragma unroll
                for (int tn = 0; tn < 4; tn++)
                    mma16816(c[tm][tn], ah, bh[tn]);
#pragma unroll
                for (int tn = 0; tn < 4; tn++)
                    mma16816(c[tm][tn], al, bh[tn]);
#pragma unroll
                for (int tn = 0; tn < 4; tn++)
                    mma16816(c[tm][tn], ah, bl[tn]);
            }
        }
        __syncthreads();
    }
#undef LOAD_CHUNK

    // ------------------ epilogue ------------------
    // c[tm][tn][{0,1}] -> row r0 = m0+wm*64+tm*16+(lane>>2),   col+{0,1}
    // c[tm][tn][{2,3}] -> row r0+8
    // col = n0 + wn*32 + tn*8 + (lane&3)*2
    if (MODE == 2) {
#pragma unroll
        for (int tm = 0; tm < 4; tm++) {
            const int r0 = m0 + wm * 64 + tm * 16 + (lane >> 2);
            float s0 = 0.0f, s1 = 0.0f;
#pragma unroll
            for (int tn = 0; tn < 4; tn++) {
                const int col = n0 + wn * 32 + tn * 8 + (lane & 3) * 2;
                float e0 = fast_exp(c[tm][tn][0]);
                float e1 = fast_exp(c[tm][tn][1]);
                float e2 = fast_exp(c[tm][tn][2]);
                float e3 = fast_exp(c[tm][tn][3]);
                s0 += e0 + e1; s1 += e2 + e3;
                __nv_bfloat16 h0 = __float2bfloat16(e0), h1 = __float2bfloat16(e1);
                __nv_bfloat16 h2 = __float2bfloat16(e2), h3 = __float2bfloat16(e3);
                __nv_bfloat16 l0 = __float2bfloat16(e0 - __bfloat162float(h0));
                __nv_bfloat16 l1 = __float2bfloat16(e1 - __bfloat162float(h1));
                __nv_bfloat16 l2 = __float2bfloat16(e2 - __bfloat162float(h2));
                __nv_bfloat16 l3 = __float2bfloat16(e3 - __bfloat162float(h3));
                long long o0 = zC + (long long)r0 * ldc + col;
                long long o1 = o0 + 8LL * ldc;
                *reinterpret_cast<uint32_t*>(Hout + o0) = pack_bf2(h0, h1);
                *reinterpret_cast<uint32_t*>(Lout + o0) = pack_bf2(l0, l1);
                *reinterpret_cast<uint32_t*>(Hout + o1) = pack_bf2(h2, h3);
                *reinterpret_cast<uint32_t*>(Lout + o1) = pack_bf2(l2, l3);
            }
            s0 += __shfl_xor_sync(0xFFFFFFFFu, s0, 1);
            s0 += __shfl_xor_sync(0xFFFFFFFFu, s0, 2);
            s1 += __shfl_xor_sync(0xFFFFFFFFu, s1, 1);
            s1 += __shfl_xor_sync(0xFFFFFFFFu, s1, 2);
            if ((lane & 3) == 0) {
                long long ro = z1 * sR1 + z2 * sR2;
                atomicAdd(rowsum + ro + r0, s0);
                atomicAdd(rowsum + ro + r0 + 8, s1);
            }
        }
    } else if (MODE == 3) {
#pragma unroll
        for (int tm = 0; tm < 4; tm++) {
            const int r0 = m0 + wm * 64 + tm * 16 + (lane >> 2);
#pragma unroll
            for (int tn = 0; tn < 4; tn++) {
                const int col = n0 + wn * 32 + tn * 8 + (lane & 3) * 2;
                const float sc = (col < 512) ? 0.125f : 1.0f;
                float v0 = (c[tm][tn][0] + bias[col])     * sc;
                float v1 = (c[tm][tn][1] + bias[col + 1]) * sc;
                float v2 = (c[tm][tn][2] + bias[col])     * sc;
                float v3 = (c[tm][tn][3] + bias[col + 1]) * sc;
                __nv_bfloat16 h0 = __float2bfloat16(v0), h1 = __float2bfloat16(v1);
                __nv_bfloat16 h2 = __float2bfloat16(v2), h3 = __float2bfloat16(v3);
                __nv_bfloat16 l0 = __float2bfloat16(v0 - __bfloat162float(h0));
                __nv_bfloat16 l1 = __float2bfloat16(v1 - __bfloat162float(h1));
                __nv_bfloat16 l2 = __float2bfloat16(v2 - __bfloat162float(h2));
                __nv_bfloat16 l3 = __float2bfloat16(v3 - __bfloat162float(h3));
                long long o0 = zC + (long long)r0 * ldc + col;
                long long o1 = o0 + 8LL * ldc;
                *reinterpret_cast<uint32_t*>(Hout + o0) = pack_bf2(h0, h1);
                *reinterpret_cast<uint32_t*>(Lout + o0) = pack_bf2(l0, l1);
                *reinterpret_cast<uint32_t*>(Hout + o1) = pack_bf2(h2, h3);
                *reinterpret_cast<uint32_t*>(Lout + o1) = pack_bf2(l2, l3);
            }
        }
    } else {
#pragma unroll
        for (int tm = 0; tm < 4; tm++) {
            const int r0 = m0 + wm * 64 + tm * 16 + (lane >> 2);
#pragma unroll
            for (int tn = 0; tn < 4; tn++) {
                const int col = n0 + wn * 32 + tn * 8 + (lane & 3) * 2;
                float2 v0 = make_float2(c[tm][tn][0], c[tm][tn][1]);
                float2 v1 = make_float2(c[tm][tn][2], c[tm][tn][3]);
                if (MODE == 1) {
                    v0.x += bias[col]; v0.y += bias[col + 1];
                    v1.x += bias[col]; v1.y += bias[col + 1];
                }
                long long o0 = zC + (long long)r0 * ldc + col;
                *reinterpret_cast<float2*>(C + o0) = v0;
                *reinterpret_cast<float2*>(C + o0 + 8LL * ldc) = v1;
            }
        }
    }
}

// ---------------------------------------------------------------------------
// prep: bv@Wo partials (grid (2,64)) + lambda (block (0,0), warp 0)
// ---------------------------------------------------------------------------
__global__ void prep_kernel(const float* __restrict__ bv, const float* __restrict__ Wo,
                            const float* __restrict__ lq1, const float* __restrict__ lk1,
                            const float* __restrict__ lq2, const float* __restrict__ lk2)
{
    if (blockIdx.x == 0 && blockIdx.y == 0 && threadIdx.x < 32) {
        int t = threadIdx.x;
        float a = lq1[t] * lk1[t] + lq1[t + 32] * lk1[t + 32];
        float b = lq2[t] * lk2[t] + lq2[t + 32] * lk2[t + 32];
#pragma unroll
        for (int o = 16; o > 0; o >>= 1) {
            a += __shfl_down_sync(0xFFFFFFFFu, a, o);
            b += __shfl_down_sync(0xFFFFFFFFu, b, o);
        }
        if (t == 0)
            g_lam = expf(a) - expf(b) + (0.8f - 0.6f);
    }
    int j  = blockIdx.x * 256 + threadIdx.x;   // 0..511
    int k0 = blockIdx.y * 128;
    float s = 0.0f;
#pragma unroll 4
    for (int k = k0; k < k0 + 128; k++)
        s = fmaf(bv[k], Wo[(long long)k * 512 + j], s);
    g_bfp[blockIdx.y * 512 + j] = s;
}

// ---------------------------------------------------------------------------
// x -> {xh,xl} (row-major) AND {xTh,xTl} (transposed per batch), one pass
// ---------------------------------------------------------------------------
__global__ void conv_x_kernel(const float* __restrict__ x)
{
    __shared__ float tile[32][33];
    const int z = blockIdx.z;                    // batch
    const int c0 = blockIdx.x * 32, r0 = blockIdx.y * 32;
    const int tx = threadIdx.x, ty = threadIdx.y;
    const float* src = x + (long long)z * 2048 * 512;
#pragma unroll
    for (int j = 0; j < 32; j += 8) {
        float v = src[(long long)(r0 + ty + j) * 512 + c0 + tx];
        tile[ty + j][tx] = v;
        long long o = ((long long)z * 2048 + r0 + ty + j) * 512 + c0 + tx;
        __nv_bfloat16 h = __float2bfloat16(v);
        g_xh[o] = h;
        g_xl[o] = __float2bfloat16(v - __bfloat162float(h));
    }
    __syncthreads();
#pragma unroll
    for (int j = 0; j < 32; j += 8) {
        float v = tile[tx][ty + j];
        long long o = (long long)z * 512 * 2048 + (long long)(c0 + ty + j) * 2048 + r0 + tx;
        __nv_bfloat16 h = __float2bfloat16(v);
        g_xTh[o] = h;
        g_xTl[o] = __float2bfloat16(v - __bfloat162float(h));
    }
}

// transpose fp32 [R,C] -> bf16 hi/lo [C,R]
__global__ void conv_trans(const float* __restrict__ src,
                           __nv_bfloat16* __restrict__ dh, __nv_bfloat16* __restrict__ dl,
                           int R, int C)
{
    __shared__ float tile[32][33];
    int c0 = blockIdx.x * 32, r0 = blockIdx.y * 32;
    int tx = threadIdx.x, ty = threadIdx.y;
#pragma unroll
    for (int j = 0; j < 32; j += 8)
        tile[ty + j][tx] = src[(long long)(r0 + ty + j) * C + c0 + tx];
    __syncthreads();
#pragma unroll
    for (int j = 0; j < 32; j += 8) {
        float v = tile[tx][ty + j];
        long long o = (long long)(c0 + ty + j) * R + r0 + tx;
        __nv_bfloat16 h = __float2bfloat16(v);
        dh[o] = h;
        dl[o] = __float2bfloat16(v - __bfloat162float(h));
    }
}

// fp32 -> bf16 hi/lo
__global__ void conv_plain(const float* __restrict__ src,
                           __nv_bfloat16* __restrict__ hi, __nv_bfloat16* __restrict__ lo,
                           long long n)
{
    long long i = (long long)blockIdx.x * 256 + threadIdx.x;
    if (i >= n) return;
    float v = src[i];
    __nv_bfloat16 h = __float2bfloat16(v);
    hi[i] = h;
    lo[i] = __float2bfloat16(v - __bfloat162float(h));
}

// t = (1/S1) o u1 - (lam/S2) o u2  -> bf16 hi/lo
__global__ void combine_kernel()
{
    long long i = (long long)blockIdx.x * 256 + threadIdx.x;   // over 4096*512
    int row = (int)(i >> 9);
    float c1 = 1.0f / g_S[row];
    float c2 = g_lam / g_S[4096 + row];
    float v = c1 * g_u[i] - c2 * g_u[i + 2097152];
    __nv_bfloat16 h = __float2bfloat16(v);
    g_th[i] = h;
    g_tl[i] = __float2bfloat16(v - __bfloat162float(h));
}

// reduce 8 split-K slabs of W2^T -> bf16 hi/lo; blocks 0-1 also build bfin
__global__ void w2_reduce_conv(const float* __restrict__ bo)
{
    int i = blockIdx.x * 256 + threadIdx.x;   // 0..262143
    float s = 0.0f;
#pragma unroll
    for (int z = 0; z < 8; z++) s += g_W2p[(long long)z * 262144 + i];
    __nv_bfloat16 h = __float2bfloat16(s);
    g_w2Th[i] = h;
    g_w2Tl[i] = __float2bfloat16(s - __bfloat162float(h));

    if (blockIdx.x < 2) {
        int j = i;  // 0..511
        float b = 0.0f;
#pragma unroll
        for (int z = 0; z < 64; z++) b += g_bfp[z * 512 + j];
        g_bfin[j] = fmaf(1.0f - g_lam, b, bo[j]);
    }
}

// ---------------------------------------------------------------------------
// Host orchestration
// ---------------------------------------------------------------------------
extern "C" void kernel_launch(void* const* d_in, const int* in_sizes, int n_in,
                              void* d_out, int out_size)
{
    const float* x    = (const float*)d_in[0];
    const float* Wqkv = (const float*)d_in[1];
    const float* bqkv = (const float*)d_in[2];
    const float* Wv   = (const float*)d_in[3];
    const float* bv   = (const float*)d_in[4];
    const float* Wo   = (const float*)d_in[5];
    const float* bo   = (const float*)d_in[6];
    const float* lq1  = (const float*)d_in[7];
    const float* lk1  = (const float*)d_in[8];
    const float* lq2  = (const float*)d_in[9];
    const float* lk2  = (const float*)d_in[10];
    float* out = (float*)d_out;

    const int SMEM = 2 * STAGE_BYTES;   // 81920
    cudaFuncSetAttribute(hmma_gemm<0>, cudaFuncAttributeMaxDynamicSharedMemorySize, SMEM);
    cudaFuncSetAttribute(hmma_gemm<1>, cudaFuncAttributeMaxDynamicSharedMemorySize, SMEM);
    cudaFuncSetAttribute(hmma_gemm<2>, cudaFuncAttributeMaxDynamicSharedMemorySize, SMEM);
    cudaFuncSetAttribute(hmma_gemm<3>, cudaFuncAttributeMaxDynamicSharedMemorySize, SMEM);

#define SYM(v, s) cudaGetSymbolAddress((void**)&v, s)
    float *W2p, *S, *u, *bfin;
    __nv_bfloat16 *qkvh, *qkvl, *xh, *xl, *xTh, *xTl, *wqTh, *wqTl;
    __nv_bfloat16 *woTh, *woTl, *wvh, *wvl, *Ehp, *Elp, *th, *tl, *w2Th, *w2Tl;
    SYM(W2p, g_W2p); SYM(S, g_S); SYM(u, g_u); SYM(bfin, g_bfin);
    SYM(qkvh, g_qkvh); SYM(qkvl, g_qkvl); SYM(xh, g_xh); SYM(xl, g_xl);
    SYM(xTh, g_xTh); SYM(xTl, g_xTl); SYM(wqTh, g_wqTh); SYM(wqTl, g_wqTl);
    SYM(woTh, g_woTh); SYM(woTl, g_woTl); SYM(wvh, g_wvh); SYM(wvl, g_wvl);
    SYM(Ehp, g_Eh); SYM(Elp, g_El); SYM(th, g_th); SYM(tl, g_tl);
    SYM(w2Th, g_w2Th); SYM(w2Tl, g_w2Tl);
#undef SYM

    const long long PS = 2048LL * 2048;

    // (0) x -> hi/lo plain + transposed
    conv_x_kernel<<<dim3(16, 64, 2), dim3(32, 8)>>>(x);
    // (1) Wqkv^T -> bf16 hi/lo
    conv_trans<<<dim3(32, 16, 1), dim3(32, 8)>>>(Wqkv, wqTh, wqTl, 512, 1024);
    // (2) qkv GEMM: bf16 hi/lo epilogue with bias + Q-scale; zeroes g_S
    hmma_gemm<3><<<dim3(8, 32, 1), 256, SMEM>>>(xh, xl, wqTh, wqTl,
        nullptr, bqkv, qkvh, qkvl, nullptr, 512, 512, 512, 1024, 1,
        0, 0, 0, 0, 0, 0, 0, 0);
    // (3) E = exp(Q K^T) for both maps+batches; z = map*2 + batch  [PROFILED]
    hmma_gemm<2><<<dim3(16, 16, 4), 256, SMEM>>>(qkvh, qkvl, qkvh + 512, qkvl + 512,
        nullptr, nullptr, Ehp, Elp, S, 256, 1024, 1024, 2048, 2,
        256, 2048LL * 1024, 256, 2048LL * 1024, 2 * PS, PS, 4096, 2048);
    // (4) prep: lambda + bv@Wo partials
    prep_kernel<<<dim3(2, 64), 256>>>(bv, Wo, lq1, lk1, lq2, lk2);
    // (5) u = E @ x for both maps+batches; z = map*2 + batch
    hmma_gemm<0><<<dim3(4, 16, 4), 256, SMEM>>>(Ehp, Elp, xTh, xTl, u,
        nullptr, nullptr, nullptr, nullptr, 2048, 2048, 2048, 512, 2,
        2 * PS, PS, 0, 512LL * 2048, 2LL * 2048 * 512, 2048LL * 512, 0, 0);
    // (6) t = c1 o u1 - c2 o u2 -> bf16 hi/lo
    combine_kernel<<<(4096 * 512) / 256, 256>>>();
    // (7,8) Wo^T, Wv -> bf16 hi/lo
    conv_trans<<<dim3(16, 256, 1), dim3(32, 8)>>>(Wo, woTh, woTl, 8192, 512);
    conv_plain<<<(512 * 8192) / 256, 256>>>(Wv, wvh, wvl, 512LL * 8192);
    // (9) W2^T = Wo^T @ Wv^T, split-K x8
    hmma_gemm<0><<<dim3(4, 4, 8), 256, SMEM>>>(woTh, woTl, wvh, wvl, W2p,
        nullptr, nullptr, nullptr, nullptr, 1024, 8192, 8192, 512, 1,
        1024, 0, 1024, 0, 262144, 0, 0, 0);
    // (10) reduce W2 slabs -> bf16 hi/lo; also bfin = (1-lam)*(bv@Wo)+bo
    w2_reduce_conv<<<1024, 256>>>(bo);
    // (11) out = t @ W2 + bfin
    hmma_gemm<1><<<dim3(4, 32, 1), 256, SMEM>>>(th, tl, w2Th, w2Tl, out, bfin,
        nullptr, nullptr, nullptr, 512, 512, 512, 512, 1,
        0, 0, 0, 0, 0, 0, 0, 0);
}

// round 10
// speedup vs baseline: 1.1437x; 1.1437x over previous
#include <cuda_runtime.h>
#include <cuda_bf16.h>
#include <cuda_fp16.h>
#include <stdint.h>

// ============================================================================
// DifferentialAttention — round 10: fp16 single-plane E + 2-term u-GEMM
//
// Round-9: NEUTRAL (469us, tensor 46%) — MMA reorder did nothing (ptxas already
// schedules). Budget: u-GEMM ~210us is dominant; its 3-split bf16 is the tax.
// Change: E stored as ONE fp16 plane scaled by 1/16 (overflow-safe to logit
// 13.9; the 1/16 cancels in t=u/S), xT in fp16 hi/lo. u-GEMM: 2 MMA terms
// (Ef*xh + Ef*xl) instead of 3, one A-fragment per tm. Injected error ~4e-4
// (fp16 rounding RMS 2^-12; model calibrated by round-5/7 measurements).
// All other GEMMs stay bf16 3-split.
//
//  out = diff @ x @ (Wv@Wo) + (1-lam)*(bv@Wo) + bo
//  t = (1/S1) o (E1@x) - (lam/S2) o (E2@x), exp fused into logits epilogue
// ============================================================================

#define SEQ 2048

// ---------------------------------------------------------------------------
// Scratch (device globals)
// ---------------------------------------------------------------------------
__device__ __align__(16) __nv_bfloat16 g_qkvh[4096 * 1024];
__device__ __align__(16) __nv_bfloat16 g_qkvl[4096 * 1024];
__device__ __align__(16) __nv_bfloat16 g_xh[4096 * 512];
__device__ __align__(16) __nv_bfloat16 g_xl[4096 * 512];
__device__ __align__(16) __half g_xT16h[2 * 512 * 2048];
__device__ __align__(16) __half g_xT16l[2 * 512 * 2048];
__device__ __align__(16) __nv_bfloat16 g_wqTh[1024 * 512];
__device__ __align__(16) __nv_bfloat16 g_wqTl[1024 * 512];
__device__ __align__(16) __nv_bfloat16 g_woTh[512 * 8192];
__device__ __align__(16) __nv_bfloat16 g_woTl[512 * 8192];
__device__ __align__(16) __nv_bfloat16 g_wvh[512 * 8192];
__device__ __align__(16) __nv_bfloat16 g_wvl[512 * 8192];
__device__ __align__(16) __half g_Ef[2LL * 2 * 2048 * 2048]; // exp/16, [map][b][S][S]
__device__ float g_S[2 * 4096];                            // rowsums/16 [map][b*S+r]
__device__ __align__(16) float g_u[2LL * 2 * 2048 * 512];  // (E/16)@x  [map][b][S][512]
__device__ __align__(16) __nv_bfloat16 g_th[4096 * 512];
__device__ __align__(16) __nv_bfloat16 g_tl[4096 * 512];
__device__ __align__(16) float g_W2p[8 * 512 * 512];
__device__ __align__(16) __nv_bfloat16 g_w2Th[512 * 512];
__device__ __align__(16) __nv_bfloat16 g_w2Tl[512 * 512];
__device__ float g_bfp[64 * 512];
__device__ float g_bfin[512];
__device__ float g_lam;

// ---------------------------------------------------------------------------
// PTX helpers (sm_80-era, valid on base sm_100)
// ---------------------------------------------------------------------------
__device__ __forceinline__ uint32_t smem_u32(const void* p) {
    uint32_t a;
    asm("{ .reg .u64 t; cvta.to.shared.u64 t, %1; cvt.u32.u64 %0, t; }"
        : "=r"(a) : "l"(p));
    return a;
}
__device__ __forceinline__ void cp16(uint32_t s, const void* g) {
    asm volatile("cp.async.cg.shared.global [%0], [%1], 16;" :: "r"(s), "l"(g));
}
#define CP_COMMIT() asm volatile("cp.async.commit_group;")
#define CP_WAIT(n)  asm volatile("cp.async.wait_group %0;" :: "n"(n))

__device__ __forceinline__ void ldsm_x4(uint32_t* r, uint32_t a) {
    asm volatile("ldmatrix.sync.aligned.m8n8.x4.shared.b16 {%0,%1,%2,%3}, [%4];"
                 : "=r"(r[0]), "=r"(r[1]), "=r"(r[2]), "=r"(r[3]) : "r"(a));
}
__device__ __forceinline__ void ldsm_x2(uint32_t* r, uint32_t a) {
    asm volatile("ldmatrix.sync.aligned.m8n8.x2.shared.b16 {%0,%1}, [%2];"
                 : "=r"(r[0]), "=r"(r[1]) : "r"(a));
}
__device__ __forceinline__ void mma16816(float* c, const uint32_t* a, const uint32_t* b) {
    asm volatile("mma.sync.aligned.m16n8k16.row.col.f32.bf16.bf16.f32 "
                 "{%0,%1,%2,%3}, {%4,%5,%6,%7}, {%8,%9}, {%0,%1,%2,%3};"
                 : "+f"(c[0]), "+f"(c[1]), "+f"(c[2]), "+f"(c[3])
                 : "r"(a[0]), "r"(a[1]), "r"(a[2]), "r"(a[3]), "r"(b[0]), "r"(b[1]));
}
__device__ __forceinline__ void mma16816h(float* c, const uint32_t* a, const uint32_t* b) {
    asm volatile("mma.sync.aligned.m16n8k16.row.col.f32.f16.f16.f32 "
                 "{%0,%1,%2,%3}, {%4,%5,%6,%7}, {%8,%9}, {%0,%1,%2,%3};"
                 : "+f"(c[0]), "+f"(c[1]), "+f"(c[2]), "+f"(c[3])
                 : "r"(a[0]), "r"(a[1]), "r"(a[2]), "r"(a[3]), "r"(b[0]), "r"(b[1]));
}

// ---------------------------------------------------------------------------
// fast exp (FMA pipe, rel err ~2.4e-6)
// ---------------------------------------------------------------------------
__device__ __forceinline__ float fast_exp(float x) {
    x = fmaxf(x, -87.0f);
    float z  = x * 1.4426950408889634f;
    float nf = z + 12582912.0f;
    int   ei = __float_as_int(nf) - 0x4B400000;
    float f  = z - (nf - 12582912.0f);
    float p  =        1.3333558146e-3f;
    p = fmaf(p, f,    9.6181291e-3f);
    p = fmaf(p, f,    5.5504108664e-2f);
    p = fmaf(p, f,    2.4022650696e-1f);
    p = fmaf(p, f,    6.9314718056e-1f);
    p = fmaf(p, f,    1.0f);
    return __int_as_float(__float_as_int(p) + (ei << 23));
}
__device__ __forceinline__ uint32_t pack_bf2(__nv_bfloat16 a, __nv_bfloat16 b) {
    return (uint32_t)__bfloat16_as_ushort(a) | ((uint32_t)__bfloat16_as_ushort(b) << 16);
}
__device__ __forceinline__ uint32_t pack_h2(__half a, __half b) {
    return (uint32_t)__half_as_ushort(a) | ((uint32_t)__half_as_ushort(b) << 16);
}

// ---------------------------------------------------------------------------
// HMMA GEMM (bf16 3-split): C = A @ B^T. Block 128x128, K-chunk 32, 8 warps.
// MODE 1: fp32 C + bias. MODE 2: exp epilogue -> ONE fp16 plane (exp/16) +
// atomicAdd rowsums (/16). MODE 3: (bias, scale cols<512 by 0.125) -> bf16
// hi/lo planes; blockIdx.x==0 also zeroes g_S. MODE 0: fp32 C.
// z = (z/zdiv, z%zdiv) dual strides. Stage: 4 planes x 10240B; 2 stages.
// ---------------------------------------------------------------------------
#define PITCH 80
#define PLANE_BYTES (128 * PITCH)       // 10240
#define STAGE_BYTES (4 * PLANE_BYTES)   // 40960

template<int MODE>
__global__ void __launch_bounds__(256, 2)
hmma_gemm(const __nv_bfloat16* __restrict__ Ah, const __nv_bfloat16* __restrict__ Al,
          const __nv_bfloat16* __restrict__ Bh, const __nv_bfloat16* __restrict__ Bl,
          float* __restrict__ C, const float* __restrict__ bias,
          __nv_bfloat16* __restrict__ Hout, __nv_bfloat16* __restrict__ Lout,
          float* __restrict__ rowsum,
          int K, int lda, int ldb, int ldc, int zdiv,
          long long sA1, long long sA2, long long sB1, long long sB2,
          long long sC1, long long sC2, long long sR1, long long sR2)
{
    extern __shared__ __align__(16) char smem[];
    const uint32_t sb = smem_u32(smem);

    const int tid = threadIdx.x;
    const int lane = tid & 31, wid = tid >> 5;
    const int wm = wid & 1, wn = wid >> 1;
    const int m0 = blockIdx.y * 128, n0 = blockIdx.x * 128;
    const int z1 = blockIdx.z / zdiv, z2 = blockIdx.z % zdiv;
    const long long zA = z1 * sA1 + z2 * sA2;
    const long long zB = z1 * sB1 + z2 * sB2;
    const long long zC = z1 * sC1 + z2 * sC2;
    Ah += zA; Al += zA; Bh += zB; Bl += zB;

    if (MODE == 3 && blockIdx.x == 0) {
        g_S[blockIdx.y * 256 + tid] = 0.0f;
    }

    const int tsel = tid >> 6;
    const __nv_bfloat16* gbase =
        (tsel == 0) ? Ah : (tsel == 1) ? Al : (tsel == 2) ? Bh : Bl;
    const int row0 = (tsel < 2) ? m0 : n0;
    const int ld   = (tsel < 2) ? lda : ldb;
    const int r64  = tid & 63;
    const uint32_t plane_off = (uint32_t)tsel * PLANE_BYTES;

    const int nch = K >> 5;

#define LOAD_CHUNK(buf, k0) do { \
    uint32_t st_ = sb + (buf) * STAGE_BYTES + plane_off; \
    _Pragma("unroll") \
    for (int it_ = 0; it_ < 8; it_++) { \
        int idx_ = r64 + it_ * 64; \
        int row_ = idx_ >> 2, seg_ = idx_ & 3; \
        const __nv_bfloat16* g_ = gbase + (long long)(row0 + row_) * ld + (k0) + seg_ * 8; \
        cp16(st_ + row_ * PITCH + seg_ * 16, g_); \
    } \
    CP_COMMIT(); \
} while (0)

    LOAD_CHUNK(0, 0);

    float c[4][4][4];
#pragma unroll
    for (int a = 0; a < 4; a++)
#pragma unroll
        for (int b = 0; b < 4; b++)
#pragma unroll
            for (int q = 0; q < 4; q++) c[a][b][q] = 0.0f;

    for (int i = 0; i < nch; i++) {
        if (i + 1 < nch) {
            LOAD_CHUNK((i + 1) & 1, (i + 1) * 32);
            CP_WAIT(1);
        } else {
            CP_WAIT(0);
        }
        __syncthreads();

        const uint32_t stg = sb + (i & 1) * STAGE_BYTES;
        const uint32_t a_row_off = (uint32_t)(wm * 64 + (lane & 15)) * PITCH + (lane >> 4) * 16;
        const uint32_t b_row_off = (uint32_t)(wn * 32 + (lane & 7)) * PITCH + ((lane >> 3) & 1) * 16;

#pragma unroll
        for (int k16 = 0; k16 < 2; k16++) {
            const uint32_t ko = k16 * 32;
            uint32_t bh[4][2], bl[4][2];
#pragma unroll
            for (int tn = 0; tn < 4; tn++) {
                ldsm_x2(bh[tn], stg + 2 * PLANE_BYTES + tn * 8 * PITCH + b_row_off + ko);
                ldsm_x2(bl[tn], stg + 3 * PLANE_BYTES + tn * 8 * PITCH + b_row_off + ko);
            }
#pragma unroll
            for (int tm = 0; tm < 4; tm++) {
                uint32_t ah[4], al[4];
                ldsm_x4(ah, stg + 0 * PLANE_BYTES + tm * 16 * PITCH + a_row_off + ko);
                ldsm_x4(al, stg + 1 * PLANE_BYTES + tm * 16 * PITCH + a_row_off + ko);
#pragma unroll
                for (int tn = 0; tn < 4; tn++)
                    mma16816(c[tm][tn], ah, bh[tn]);
#pragma unroll
                for (int tn = 0; tn < 4; tn++)
                    mma16816(c[tm][tn], al, bh[tn]);
#pragma unroll
                for (int tn = 0; tn < 4; tn++)
                    mma16816(c[tm][tn], ah, bl[tn]);
            }
        }
        __syncthreads();
    }
#undef LOAD_CHUNK

    // ------------------ epilogue ------------------
    if (MODE == 2) {
        __half* Ef = reinterpret_cast<__half*>(Hout);
#pragma unroll
        for (int tm = 0; tm < 4; tm++) {
            const int r0 = m0 + wm * 64 + tm * 16 + (lane >> 2);
            float s0 = 0.0f, s1 = 0.0f;
#pragma unroll
            for (int tn = 0; tn < 4; tn++) {
                const int col = n0 + wn * 32 + tn * 8 + (lane & 3) * 2;
                float e0 = fast_exp(c[tm][tn][0]) * 0.0625f;
                float e1 = fast_exp(c[tm][tn][1]) * 0.0625f;
                float e2 = fast_exp(c[tm][tn][2]) * 0.0625f;
                float e3 = fast_exp(c[tm][tn][3]) * 0.0625f;
                s0 += e0 + e1; s1 += e2 + e3;
                long long o0 = zC + (long long)r0 * ldc + col;
                long long o1 = o0 + 8LL * ldc;
                *reinterpret_cast<uint32_t*>(Ef + o0) =
                    pack_h2(__float2half(e0), __float2half(e1));
                *reinterpret_cast<uint32_t*>(Ef + o1) =
                    pack_h2(__float2half(e2), __float2half(e3));
            }
            s0 += __shfl_xor_sync(0xFFFFFFFFu, s0, 1);
            s0 += __shfl_xor_sync(0xFFFFFFFFu, s0, 2);
            s1 += __shfl_xor_sync(0xFFFFFFFFu, s1, 1);
            s1 += __shfl_xor_sync(0xFFFFFFFFu, s1, 2);
            if ((lane & 3) == 0) {
                long long ro = z1 * sR1 + z2 * sR2;
                atomicAdd(rowsum + ro + r0, s0);
                atomicAdd(rowsum + ro + r0 + 8, s1);
            }
        }
    } else if (MODE == 3) {
#pragma unroll
        for (int tm = 0; tm < 4; tm++) {
            const int r0 = m0 + wm * 64 + tm * 16 + (lane >> 2);
#pragma unroll
            for (int tn = 0; tn < 4; tn++) {
                const int col = n0 + wn * 32 + tn * 8 + (lane & 3) * 2;
                const float sc = (col < 512) ? 0.125f : 1.0f;
                float v0 = (c[tm][tn][0] + bias[col])     * sc;
                float v1 = (c[tm][tn][1] + bias[col + 1]) * sc;
                float v2 = (c[tm][tn][2] + bias[col])     * sc;
                float v3 = (c[tm][tn][3] + bias[col + 1]) * sc;
                __nv_bfloat16 h0 = __float2bfloat16(v0), h1 = __float2bfloat16(v1);
                __nv_bfloat16 h2 = __float2bfloat16(v2), h3 = __float2bfloat16(v3);
                __nv_bfloat16 l0 = __float2bfloat16(v0 - __bfloat162float(h0));
                __nv_bfloat16 l1 = __float2bfloat16(v1 - __bfloat162float(h1));
                __nv_bfloat16 l2 = __float2bfloat16(v2 - __bfloat162float(h2));
                __nv_bfloat16 l3 = __float2bfloat16(v3 - __bfloat162float(h3));
                long long o0 = zC + (long long)r0 * ldc + col;
                long long o1 = o0 + 8LL * ldc;
                *reinterpret_cast<uint32_t*>(Hout + o0) = pack_bf2(h0, h1);
                *reinterpret_cast<uint32_t*>(Lout + o0) = pack_bf2(l0, l1);
                *reinterpret_cast<uint32_t*>(Hout + o1) = pack_bf2(h2, h3);
                *reinterpret_cast<uint32_t*>(Lout + o1) = pack_bf2(l2, l3);
            }
        }
    } else {
#pragma unroll
        for (int tm = 0; tm < 4; tm++) {
            const int r0 = m0 + wm * 64 + tm * 16 + (lane >> 2);
#pragma unroll
            for (int tn = 0; tn < 4; tn++) {
                const int col = n0 + wn * 32 + tn * 8 + (lane & 3) * 2;
                float2 v0 = make_float2(c[tm][tn][0], c[tm][tn][1]);
                float2 v1 = make_float2(c[tm][tn][2], c[tm][tn][3]);
                if (MODE == 1) {
                    v0.x += bias[col]; v0.y += bias[col + 1];
                    v1.x += bias[col]; v1.y += bias[col + 1];
                }
                long long o0 = zC + (long long)r0 * ldc + col;
                *reinterpret_cast<float2*>(C + o0) = v0;
                *reinterpret_cast<float2*>(C + o0 + 8LL * ldc) = v1;
            }
        }
    }
}

// ---------------------------------------------------------------------------
// u-GEMM (fp16, 2-term): C[M,N] = A @ B^T with A = Ef [M,K] fp16 single plane,
// B = xT fp16 hi/lo [N,K]. Per tm: ONE ldsm_x4, 8 MMAs (ah*bh + ah*bl).
// 3 smem planes (A, Bh, Bl); stage 30720B x 2. fp32 C out.
// ---------------------------------------------------------------------------
#define USTAGE_BYTES (3 * PLANE_BYTES)  // 30720

__global__ void __launch_bounds__(256, 2)
u_gemm(const __half* __restrict__ A, const __half* __restrict__ Bh16,
       const __half* __restrict__ Bl16, float* __restrict__ C,
       int K, int lda, int ldb, int ldc, int zdiv,
       long long sA1, long long sA2, long long sB1, long long sB2,
       long long sC1, long long sC2)
{
    extern __shared__ __align__(16) char smem[];
    const uint32_t sb = smem_u32(smem);

    const int tid = threadIdx.x;
    const int lane = tid & 31, wid = tid >> 5;
    const int wm = wid & 1, wn = wid >> 1;
    const int m0 = blockIdx.y * 128, n0 = blockIdx.x * 128;
    const int z1 = blockIdx.z / zdiv, z2 = blockIdx.z % zdiv;
    A    += z1 * sA1 + z2 * sA2;
    Bh16 += z1 * sB1 + z2 * sB2;
    Bl16 += z1 * sB1 + z2 * sB2;
    const long long zC = z1 * sC1 + z2 * sC2;

    // loader: planes 0=A, 1=Bh, 2=Bl; 64 threads each; tsel==3 idle
    const int tsel = tid >> 6;
    const __half* gbase = (tsel == 0) ? A : (tsel == 1) ? Bh16 : Bl16;
    const int row0 = (tsel == 0) ? m0 : n0;
    const int ld   = (tsel == 0) ? lda : ldb;
    const int r64  = tid & 63;
    const uint32_t plane_off = (uint32_t)tsel * PLANE_BYTES;

    const int nch = K >> 5;

#define ULOAD(buf, k0) do { \
    if (tsel < 3) { \
        uint32_t st_ = sb + (buf) * USTAGE_BYTES + plane_off; \
        _Pragma("unroll") \
        for (int it_ = 0; it_ < 8; it_++) { \
            int idx_ = r64 + it_ * 64; \
            int row_ = idx_ >> 2, seg_ = idx_ & 3; \
            const __half* g_ = gbase + (long long)(row0 + row_) * ld + (k0) + seg_ * 8; \
            cp16(st_ + row_ * PITCH + seg_ * 16, g_); \
        } \
    } \
    CP_COMMIT(); \
} while (0)

    ULOAD(0, 0);

    float c[4][4][4];
#pragma unroll
    for (int a = 0; a < 4; a++)
#pragma unroll
        for (int b = 0; b < 4; b++)
#pragma unroll
            for (int q = 0; q < 4; q++) c[a][b][q] = 0.0f;

    for (int i = 0; i < nch; i++) {
        if (i + 1 < nch) {
            ULOAD((i + 1) & 1, (i + 1) * 32);
            CP_WAIT(1);
        } else {
            CP_WAIT(0);
        }
        __syncthreads();

        const uint32_t stg = sb + (i & 1) * USTAGE_BYTES;
        const uint32_t a_row_off = (uint32_t)(wm * 64 + (lane & 15)) * PITCH + (lane >> 4) * 16;
        const uint32_t b_row_off = (uint32_t)(wn * 32 + (lane & 7)) * PITCH + ((lane >> 3) & 1) * 16;

#pragma unroll
        for (int k16 = 0; k16 < 2; k16++) {
            const uint32_t ko = k16 * 32;
            uint32_t bh[4][2], bl[4][2];
#pragma unroll
            for (int tn = 0; tn < 4; tn++) {
                ldsm_x2(bh[tn], stg + 1 * PLANE_BYTES + tn * 8 * PITCH + b_row_off + ko);
                ldsm_x2(bl[tn], stg + 2 * PLANE_BYTES + tn * 8 * PITCH + b_row_off + ko);
            }
#pragma unroll
            for (int tm = 0; tm < 4; tm++) {
                uint32_t ah[4];
                ldsm_x4(ah, stg + 0 * PLANE_BYTES + tm * 16 * PITCH + a_row_off + ko);
#pragma unroll
                for (int tn = 0; tn < 4; tn++)
                    mma16816h(c[tm][tn], ah, bh[tn]);
#pragma unroll
                for (int tn = 0; tn < 4; tn++)
                    mma16816h(c[tm][tn], ah, bl[tn]);
            }
        }
        __syncthreads();
    }
#undef ULOAD

#pragma unroll
    for (int tm = 0; tm < 4; tm++) {
        const int r0 = m0 + wm * 64 + tm * 16 + (lane >> 2);
#pragma unroll
        for (int tn = 0; tn < 4; tn++) {
            const int col = n0 + wn * 32 + tn * 8 + (lane & 3) * 2;
            long long o0 = zC + (long long)r0 * ldc + col;
            *reinterpret_cast<float2*>(C + o0) = make_float2(c[tm][tn][0], c[tm][tn][1]);
            *reinterpret_cast<float2*>(C + o0 + 8LL * ldc) = make_float2(c[tm][tn][2], c[tm][tn][3]);
        }
    }
}

// ---------------------------------------------------------------------------
// prep: bv@Wo partials (grid (2,64)) + lambda (block (0,0), warp 0)
// ---------------------------------------------------------------------------
__global__ void prep_kernel(const float* __restrict__ bv, const float* __restrict__ Wo,
                            const float* __restrict__ lq1, const float* __restrict__ lk1,
                            const float* __restrict__ lq2, const float* __restrict__ lk2)
{
    if (blockIdx.x == 0 && blockIdx.y == 0 && threadIdx.x < 32) {
        int t = threadIdx.x;
        float a = lq1[t] * lk1[t] + lq1[t + 32] * lk1[t + 32];
        float b = lq2[t] * lk2[t] + lq2[t + 32] * lk2[t + 32];
#pragma unroll
        for (int o = 16; o > 0; o >>= 1) {
            a += __shfl_down_sync(0xFFFFFFFFu, a, o);
            b += __shfl_down_sync(0xFFFFFFFFu, b, o);
        }
        if (t == 0)
            g_lam = expf(a) - expf(b) + (0.8f - 0.6f);
    }
    int j  = blockIdx.x * 256 + threadIdx.x;   // 0..511
    int k0 = blockIdx.y * 128;
    float s = 0.0f;
#pragma unroll 4
    for (int k = k0; k < k0 + 128; k++)
        s = fmaf(bv[k], Wo[(long long)k * 512 + j], s);
    g_bfp[blockIdx.y * 512 + j] = s;
}

// ---------------------------------------------------------------------------
// x -> {xh,xl} bf16 (row-major) AND {xT16h,xT16l} fp16 (transposed per batch)
// ---------------------------------------------------------------------------
__global__ void conv_x_kernel(const float* __restrict__ x)
{
    __shared__ float tile[32][33];
    const int z = blockIdx.z;
    const int c0 = blockIdx.x * 32, r0 = blockIdx.y * 32;
    const int tx = threadIdx.x, ty = threadIdx.y;
    const float* src = x + (long long)z * 2048 * 512;
#pragma unroll
    for (int j = 0; j < 32; j += 8) {
        float v = src[(long long)(r0 + ty + j) * 512 + c0 + tx];
        tile[ty + j][tx] = v;
        long long o = ((long long)z * 2048 + r0 + ty + j) * 512 + c0 + tx;
        __nv_bfloat16 h = __float2bfloat16(v);
        g_xh[o] = h;
        g_xl[o] = __float2bfloat16(v - __bfloat162float(h));
    }
    __syncthreads();
#pragma unroll
    for (int j = 0; j < 32; j += 8) {
        float v = tile[tx][ty + j];
        long long o = (long long)z * 512 * 2048 + (long long)(c0 + ty + j) * 2048 + r0 + tx;
        __half h = __float2half(v);
        g_xT16h[o] = h;
        g_xT16l[o] = __float2half(v - __half2float(h));
    }
}

// transpose fp32 [R,C] -> bf16 hi/lo [C,R]
__global__ void conv_trans(const float* __restrict__ src,
                           __nv_bfloat16* __restrict__ dh, __nv_bfloat16* __restrict__ dl,
                           int R, int C)
{
    __shared__ float tile[32][33];
    int c0 = blockIdx.x * 32, r0 = blockIdx.y * 32;
    int tx = threadIdx.x, ty = threadIdx.y;
#pragma unroll
    for (int j = 0; j < 32; j += 8)
        tile[ty + j][tx] = src[(long long)(r0 + ty + j) * C + c0 + tx];
    __syncthreads();
#pragma unroll
    for (int j = 0; j < 32; j += 8) {
        float v = tile[tx][ty + j];
        long long o = (long long)(c0 + ty + j) * R + r0 + tx;
        __nv_bfloat16 h = __float2bfloat16(v);
        dh[o] = h;
        dl[o] = __float2bfloat16(v - __bfloat162float(h));
    }
}

// fp32 -> bf16 hi/lo
__global__ void conv_plain(const float* __restrict__ src,
                           __nv_bfloat16* __restrict__ hi, __nv_bfloat16* __restrict__ lo,
                           long long n)
{
    long long i = (long long)blockIdx.x * 256 + threadIdx.x;
    if (i >= n) return;
    float v = src[i];
    __nv_bfloat16 h = __float2bfloat16(v);
    hi[i] = h;
    lo[i] = __float2bfloat16(v - __bfloat162float(h));
}

// t = (1/S1) o u1 - (lam/S2) o u2  -> bf16 hi/lo  (1/16 scaling cancels)
__global__ void combine_kernel()
{
    long long i = (long long)blockIdx.x * 256 + threadIdx.x;   // over 4096*512
    int row = (int)(i >> 9);
    float c1 = 1.0f / g_S[row];
    float c2 = g_lam / g_S[4096 + row];
    float v = c1 * g_u[i] - c2 * g_u[i + 2097152];
    __nv_bfloat16 h = __float2bfloat16(v);
    g_th[i] = h;
    g_tl[i] = __float2bfloat16(v - __bfloat162float(h));
}

// reduce 8 split-K slabs of W2^T -> bf16 hi/lo; blocks 0-1 also build bfin
__global__ void w2_reduce_conv(const float* __restrict__ bo)
{
    int i = blockIdx.x * 256 + threadIdx.x;   // 0..262143
    float s = 0.0f;
#pragma unroll
    for (int z = 0; z < 8; z++) s += g_W2p[(long long)z * 262144 + i];
    __nv_bfloat16 h = __float2bfloat16(s);
    g_w2Th[i] = h;
    g_w2Tl[i] = __float2bfloat16(s - __bfloat162float(h));

    if (blockIdx.x < 2) {
        int j = i;  // 0..511
        float b = 0.0f;
#pragma unroll
        for (int z = 0; z < 64; z++) b += g_bfp[z * 512 + j];
        g_bfin[j] = fmaf(1.0f - g_lam, b, bo[j]);
    }
}

// ---------------------------------------------------------------------------
// Host orchestration
// ---------------------------------------------------------------------------
extern "C" void kernel_launch(void* const* d_in, const int* in_sizes, int n_in,
                              void* d_out, int out_size)
{
    const float* x    = (const float*)d_in[0];
    const float* Wqkv = (const float*)d_in[1];
    const float* bqkv = (const float*)d_in[2];
    const float* Wv   = (const float*)d_in[3];
    const float* bv   = (const float*)d_in[4];
    const float* Wo   = (const float*)d_in[5];
    const float* bo   = (const float*)d_in[6];
    const float* lq1  = (const float*)d_in[7];
    const float* lk1  = (const float*)d_in[8];
    const float* lq2  = (const float*)d_in[9];
    const float* lk2  = (const float*)d_in[10];
    float* out = (float*)d_out;

    const int SMEM  = 2 * STAGE_BYTES;    // 81920
    const int USMEM = 2 * USTAGE_BYTES;   // 61440
    cudaFuncSetAttribute(hmma_gemm<0>, cudaFuncAttributeMaxDynamicSharedMemorySize, SMEM);
    cudaFuncSetAttribute(hmma_gemm<1>, cudaFuncAttributeMaxDynamicSharedMemorySize, SMEM);
    cudaFuncSetAttribute(hmma_gemm<2>, cudaFuncAttributeMaxDynamicSharedMemorySize, SMEM);
    cudaFuncSetAttribute(hmma_gemm<3>, cudaFuncAttributeMaxDynamicSharedMemorySize, SMEM);
    cudaFuncSetAttribute(u_gemm, cudaFuncAttributeMaxDynamicSharedMemorySize, USMEM);

#define SYM(v, s) cudaGetSymbolAddress((void**)&v, s)
    float *W2p, *S, *u, *bfin;
    __nv_bfloat16 *qkvh, *qkvl, *xh, *xl, *wqTh, *wqTl;
    __nv_bfloat16 *woTh, *woTl, *wvh, *wvl, *th, *tl, *w2Th, *w2Tl;
    __half *Ef, *xT16h, *xT16l;
    SYM(W2p, g_W2p); SYM(S, g_S); SYM(u, g_u); SYM(bfin, g_bfin);
    SYM(qkvh, g_qkvh); SYM(qkvl, g_qkvl); SYM(xh, g_xh); SYM(xl, g_xl);
    SYM(xT16h, g_xT16h); SYM(xT16l, g_xT16l); SYM(wqTh, g_wqTh); SYM(wqTl, g_wqTl);
    SYM(woTh, g_woTh); SYM(woTl, g_woTl); SYM(wvh, g_wvh); SYM(wvl, g_wvl);
    SYM(Ef, g_Ef); SYM(th, g_th); SYM(tl, g_tl);
    SYM(w2Th, g_w2Th); SYM(w2Tl, g_w2Tl);
#undef SYM

    const long long PS = 2048LL * 2048;

    // (0) x -> bf16 planes + fp16 transposed planes
    conv_x_kernel<<<dim3(16, 64, 2), dim3(32, 8)>>>(x);
    // (1) Wqkv^T -> bf16 hi/lo
    conv_trans<<<dim3(32, 16, 1), dim3(32, 8)>>>(Wqkv, wqTh, wqTl, 512, 1024);
    // (2) qkv GEMM: bf16 hi/lo epilogue with bias + Q-scale; zeroes g_S
    hmma_gemm<3><<<dim3(8, 32, 1), 256, SMEM>>>(xh, xl, wqTh, wqTl,
        nullptr, bqkv, qkvh, qkvl, nullptr, 512, 512, 512, 1024, 1,
        0, 0, 0, 0, 0, 0, 0, 0);
    // (3) E = exp(Q K^T)/16 fp16 plane + rowsums/16; z = map*2 + batch  [PROFILED]
    hmma_gemm<2><<<dim3(16, 16, 4), 256, SMEM>>>(qkvh, qkvl, qkvh + 512, qkvl + 512,
        nullptr, nullptr, (__nv_bfloat16*)Ef, nullptr, S, 256, 1024, 1024, 2048, 2,
        256, 2048LL * 1024, 256, 2048LL * 1024, 2 * PS, PS, 4096, 2048);
    // (4) prep: lambda + bv@Wo partials
    prep_kernel<<<dim3(2, 64), 256>>>(bv, Wo, lq1, lk1, lq2, lk2);
    // (5) u = Ef @ x (fp16, 2-term); z = map*2 + batch
    u_gemm<<<dim3(4, 16, 4), 256, USMEM>>>(Ef, xT16h, xT16l, u,
        2048, 2048, 2048, 512, 2,
        2 * PS, PS, 0, 512LL * 2048, 2LL * 2048 * 512, 2048LL * 512);
    // (6) t = c1 o u1 - c2 o u2 -> bf16 hi/lo
    combine_kernel<<<(4096 * 512) / 256, 256>>>();
    // (7,8) Wo^T, Wv -> bf16 hi/lo
    conv_trans<<<dim3(16, 256, 1), dim3(32, 8)>>>(Wo, woTh, woTl, 8192, 512);
    conv_plain<<<(512 * 8192) / 256, 256>>>(Wv, wvh, wvl, 512LL * 8192);
    // (9) W2^T = Wo^T @ Wv^T, split-K x8
    hmma_gemm<0><<<dim3(4, 4, 8), 256, SMEM>>>(woTh, woTl, wvh, wvl, W2p,
        nullptr, nullptr, nullptr, nullptr, 1024, 8192, 8192, 512, 1,
        1024, 0, 1024, 0, 262144, 0, 0, 0);
    // (10) reduce W2 slabs -> bf16 hi/lo; also bfin = (1-lam)*(bv@Wo)+bo
    w2_reduce_conv<<<1024, 256>>>(bo);
    // (11) out = t @ W2 + bfin
    hmma_gemm<1><<<dim3(4, 32, 1), 256, SMEM>>>(th, tl, w2Th, w2Tl, out, bfin,
        nullptr, nullptr, nullptr, 512, 512, 512, 512, 1,
        0, 0, 0, 0, 0, 0, 0, 0);
}

// round 11
// speedup vs baseline: 1.3085x; 1.1441x over previous
#include <cuda_runtime.h>
#include <cuda_bf16.h>
#include <cuda_fp16.h>
#include <stdint.h>

// ============================================================================
// DifferentialAttention — round 11: 1-term u-GEMM (drop xl correction plane)
//
// Round-10: WIN 469->410us, rel_err 1.77e-4 (error model calibrated: measured
// ~0.7x per-element RMS estimate due to K-sum averaging). u-GEMM still the
// largest phase. Change: u = Ef @ xh16 single term — the dropped Ef*xl term
// corrects x's fp16 rounding (2^-12), injecting ~1-2e-4. Predicted total
// rel_err ~3e-4 (3x inside gate). u-GEMM MMAs/iter 32->16, LDSM 20->12.
// E-GEMM stays bf16 3-split (logit error amplified by exp — not safe to cut).
//
//  out = diff @ x @ (Wv@Wo) + (1-lam)*(bv@Wo) + bo
//  t = (1/S1) o (E1@x) - (lam/S2) o (E2@x), exp fused into logits epilogue,
//  E stored as fp16 exp/16 (scale cancels in t = u/S).
// ============================================================================

#define SEQ 2048

// ---------------------------------------------------------------------------
// Scratch (device globals)
// ---------------------------------------------------------------------------
__device__ __align__(16) __nv_bfloat16 g_qkvh[4096 * 1024];
__device__ __align__(16) __nv_bfloat16 g_qkvl[4096 * 1024];
__device__ __align__(16) __nv_bfloat16 g_xh[4096 * 512];
__device__ __align__(16) __nv_bfloat16 g_xl[4096 * 512];
__device__ __align__(16) __half g_xT16h[2 * 512 * 2048];
__device__ __align__(16) __nv_bfloat16 g_wqTh[1024 * 512];
__device__ __align__(16) __nv_bfloat16 g_wqTl[1024 * 512];
__device__ __align__(16) __nv_bfloat16 g_woTh[512 * 8192];
__device__ __align__(16) __nv_bfloat16 g_woTl[512 * 8192];
__device__ __align__(16) __nv_bfloat16 g_wvh[512 * 8192];
__device__ __align__(16) __nv_bfloat16 g_wvl[512 * 8192];
__device__ __align__(16) __half g_Ef[2LL * 2 * 2048 * 2048]; // exp/16, [map][b][S][S]
__device__ float g_S[2 * 4096];                            // rowsums/16 [map][b*S+r]
__device__ __align__(16) float g_u[2LL * 2 * 2048 * 512];  // (E/16)@x  [map][b][S][512]
__device__ __align__(16) __nv_bfloat16 g_th[4096 * 512];
__device__ __align__(16) __nv_bfloat16 g_tl[4096 * 512];
__device__ __align__(16) float g_W2p[8 * 512 * 512];
__device__ __align__(16) __nv_bfloat16 g_w2Th[512 * 512];
__device__ __align__(16) __nv_bfloat16 g_w2Tl[512 * 512];
__device__ float g_bfp[64 * 512];
__device__ float g_bfin[512];
__device__ float g_lam;

// ---------------------------------------------------------------------------
// PTX helpers (sm_80-era, valid on base sm_100)
// ---------------------------------------------------------------------------
__device__ __forceinline__ uint32_t smem_u32(const void* p) {
    uint32_t a;
    asm("{ .reg .u64 t; cvta.to.shared.u64 t, %1; cvt.u32.u64 %0, t; }"
        : "=r"(a) : "l"(p));
    return a;
}
__device__ __forceinline__ void cp16(uint32_t s, const void* g) {
    asm volatile("cp.async.cg.shared.global [%0], [%1], 16;" :: "r"(s), "l"(g));
}
#define CP_COMMIT() asm volatile("cp.async.commit_group;")
#define CP_WAIT(n)  asm volatile("cp.async.wait_group %0;" :: "n"(n))

__device__ __forceinline__ void ldsm_x4(uint32_t* r, uint32_t a) {
    asm volatile("ldmatrix.sync.aligned.m8n8.x4.shared.b16 {%0,%1,%2,%3}, [%4];"
                 : "=r"(r[0]), "=r"(r[1]), "=r"(r[2]), "=r"(r[3]) : "r"(a));
}
__device__ __forceinline__ void ldsm_x2(uint32_t* r, uint32_t a) {
    asm volatile("ldmatrix.sync.aligned.m8n8.x2.shared.b16 {%0,%1}, [%2];"
                 : "=r"(r[0]), "=r"(r[1]) : "r"(a));
}
__device__ __forceinline__ void mma16816(float* c, const uint32_t* a, const uint32_t* b) {
    asm volatile("mma.sync.aligned.m16n8k16.row.col.f32.bf16.bf16.f32 "
                 "{%0,%1,%2,%3}, {%4,%5,%6,%7}, {%8,%9}, {%0,%1,%2,%3};"
                 : "+f"(c[0]), "+f"(c[1]), "+f"(c[2]), "+f"(c[3])
                 : "r"(a[0]), "r"(a[1]), "r"(a[2]), "r"(a[3]), "r"(b[0]), "r"(b[1]));
}
__device__ __forceinline__ void mma16816h(float* c, const uint32_t* a, const uint32_t* b) {
    asm volatile("mma.sync.aligned.m16n8k16.row.col.f32.f16.f16.f32 "
                 "{%0,%1,%2,%3}, {%4,%5,%6,%7}, {%8,%9}, {%0,%1,%2,%3};"
                 : "+f"(c[0]), "+f"(c[1]), "+f"(c[2]), "+f"(c[3])
                 : "r"(a[0]), "r"(a[1]), "r"(a[2]), "r"(a[3]), "r"(b[0]), "r"(b[1]));
}

// ---------------------------------------------------------------------------
// fast exp (FMA pipe, rel err ~2.4e-6)
// ---------------------------------------------------------------------------
__device__ __forceinline__ float fast_exp(float x) {
    x = fmaxf(x, -87.0f);
    float z  = x * 1.4426950408889634f;
    float nf = z + 12582912.0f;
    int   ei = __float_as_int(nf) - 0x4B400000;
    float f  = z - (nf - 12582912.0f);
    float p  =        1.3333558146e-3f;
    p = fmaf(p, f,    9.6181291e-3f);
    p = fmaf(p, f,    5.5504108664e-2f);
    p = fmaf(p, f,    2.4022650696e-1f);
    p = fmaf(p, f,    6.9314718056e-1f);
    p = fmaf(p, f,    1.0f);
    return __int_as_float(__float_as_int(p) + (ei << 23));
}
__device__ __forceinline__ uint32_t pack_bf2(__nv_bfloat16 a, __nv_bfloat16 b) {
    return (uint32_t)__bfloat16_as_ushort(a) | ((uint32_t)__bfloat16_as_ushort(b) << 16);
}
__device__ __forceinline__ uint32_t pack_h2(__half a, __half b) {
    return (uint32_t)__half_as_ushort(a) | ((uint32_t)__half_as_ushort(b) << 16);
}

// ---------------------------------------------------------------------------
// HMMA GEMM (bf16 3-split): C = A @ B^T. Block 128x128, K-chunk 32, 8 warps.
// MODE 1: fp32 C + bias. MODE 2: exp epilogue -> ONE fp16 plane (exp/16) +
// atomicAdd rowsums (/16). MODE 3: (bias, scale cols<512 by 0.125) -> bf16
// hi/lo planes; blockIdx.x==0 also zeroes g_S. MODE 0: fp32 C.
// z = (z/zdiv, z%zdiv) dual strides. Stage: 4 planes x 10240B; 2 stages.
// ---------------------------------------------------------------------------
#define PITCH 80
#define PLANE_BYTES (128 * PITCH)       // 10240
#define STAGE_BYTES (4 * PLANE_BYTES)   // 40960

template<int MODE>
__global__ void __launch_bounds__(256, 2)
hmma_gemm(const __nv_bfloat16* __restrict__ Ah, const __nv_bfloat16* __restrict__ Al,
          const __nv_bfloat16* __restrict__ Bh, const __nv_bfloat16* __restrict__ Bl,
          float* __restrict__ C, const float* __restrict__ bias,
          __nv_bfloat16* __restrict__ Hout, __nv_bfloat16* __restrict__ Lout,
          float* __restrict__ rowsum,
          int K, int lda, int ldb, int ldc, int zdiv,
          long long sA1, long long sA2, long long sB1, long long sB2,
          long long sC1, long long sC2, long long sR1, long long sR2)
{
    extern __shared__ __align__(16) char smem[];
    const uint32_t sb = smem_u32(smem);

    const int tid = threadIdx.x;
    const int lane = tid & 31, wid = tid >> 5;
    const int wm = wid & 1, wn = wid >> 1;
    const int m0 = blockIdx.y * 128, n0 = blockIdx.x * 128;
    const int z1 = blockIdx.z / zdiv, z2 = blockIdx.z % zdiv;
    const long long zA = z1 * sA1 + z2 * sA2;
    const long long zB = z1 * sB1 + z2 * sB2;
    const long long zC = z1 * sC1 + z2 * sC2;
    Ah += zA; Al += zA; Bh += zB; Bl += zB;

    if (MODE == 3 && blockIdx.x == 0) {
        g_S[blockIdx.y * 256 + tid] = 0.0f;
    }

    const int tsel = tid >> 6;
    const __nv_bfloat16* gbase =
        (tsel == 0) ? Ah : (tsel == 1) ? Al : (tsel == 2) ? Bh : Bl;
    const int row0 = (tsel < 2) ? m0 : n0;
    const int ld   = (tsel < 2) ? lda : ldb;
    const int r64  = tid & 63;
    const uint32_t plane_off = (uint32_t)tsel * PLANE_BYTES;

    const int nch = K >> 5;

#define LOAD_CHUNK(buf, k0) do { \
    uint32_t st_ = sb + (buf) * STAGE_BYTES + plane_off; \
    _Pragma("unroll") \
    for (int it_ = 0; it_ < 8; it_++) { \
        int idx_ = r64 + it_ * 64; \
        int row_ = idx_ >> 2, seg_ = idx_ & 3; \
        const __nv_bfloat16* g_ = gbase + (long long)(row0 + row_) * ld + (k0) + seg_ * 8; \
        cp16(st_ + row_ * PITCH + seg_ * 16, g_); \
    } \
    CP_COMMIT(); \
} while (0)

    LOAD_CHUNK(0, 0);

    float c[4][4][4];
#pragma unroll
    for (int a = 0; a < 4; a++)
#pragma unroll
        for (int b = 0; b < 4; b++)
#pragma unroll
            for (int q = 0; q < 4; q++) c[a][b][q] = 0.0f;

    for (int i = 0; i < nch; i++) {
        if (i + 1 < nch) {
            LOAD_CHUNK((i + 1) & 1, (i + 1) * 32);
            CP_WAIT(1);
        } else {
            CP_WAIT(0);
        }
        __syncthreads();

        const uint32_t stg = sb + (i & 1) * STAGE_BYTES;
        const uint32_t a_row_off = (uint32_t)(wm * 64 + (lane & 15)) * PITCH + (lane >> 4) * 16;
        const uint32_t b_row_off = (uint32_t)(wn * 32 + (lane & 7)) * PITCH + ((lane >> 3) & 1) * 16;

#pragma unroll
        for (int k16 = 0; k16 < 2; k16++) {
            const uint32_t ko = k16 * 32;
            uint32_t bh[4][2], bl[4][2];
#pragma unroll
            for (int tn = 0; tn < 4; tn++) {
                ldsm_x2(bh[tn], stg + 2 * PLANE_BYTES + tn * 8 * PITCH + b_row_off + ko);
                ldsm_x2(bl[tn], stg + 3 * PLANE_BYTES + tn * 8 * PITCH + b_row_off + ko);
            }
#pragma unroll
            for (int tm = 0; tm < 4; tm++) {
                uint32_t ah[4], al[4];
                ldsm_x4(ah, stg + 0 * PLANE_BYTES + tm * 16 * PITCH + a_row_off + ko);
                ldsm_x4(al, stg + 1 * PLANE_BYTES + tm * 16 * PITCH + a_row_off + ko);
#pragma unroll
                for (int tn = 0; tn < 4; tn++)
                    mma16816(c[tm][tn], ah, bh[tn]);
#pragma unroll
                for (int tn = 0; tn < 4; tn++)
                    mma16816(c[tm][tn], al, bh[tn]);
#pragma unroll
                for (int tn = 0; tn < 4; tn++)
                    mma16816(c[tm][tn], ah, bl[tn]);
            }
        }
        __syncthreads();
    }
#undef LOAD_CHUNK

    // ------------------ epilogue ------------------
    if (MODE == 2) {
        __half* Ef = reinterpret_cast<__half*>(Hout);
#pragma unroll
        for (int tm = 0; tm < 4; tm++) {
            const int r0 = m0 + wm * 64 + tm * 16 + (lane >> 2);
            float s0 = 0.0f, s1 = 0.0f;
#pragma unroll
            for (int tn = 0; tn < 4; tn++) {
                const int col = n0 + wn * 32 + tn * 8 + (lane & 3) * 2;
                float e0 = fast_exp(c[tm][tn][0]) * 0.0625f;
                float e1 = fast_exp(c[tm][tn][1]) * 0.0625f;
                float e2 = fast_exp(c[tm][tn][2]) * 0.0625f;
                float e3 = fast_exp(c[tm][tn][3]) * 0.0625f;
                s0 += e0 + e1; s1 += e2 + e3;
                long long o0 = zC + (long long)r0 * ldc + col;
                long long o1 = o0 + 8LL * ldc;
                *reinterpret_cast<uint32_t*>(Ef + o0) =
                    pack_h2(__float2half(e0), __float2half(e1));
                *reinterpret_cast<uint32_t*>(Ef + o1) =
                    pack_h2(__float2half(e2), __float2half(e3));
            }
            s0 += __shfl_xor_sync(0xFFFFFFFFu, s0, 1);
            s0 += __shfl_xor_sync(0xFFFFFFFFu, s0, 2);
            s1 += __shfl_xor_sync(0xFFFFFFFFu, s1, 1);
            s1 += __shfl_xor_sync(0xFFFFFFFFu, s1, 2);
            if ((lane & 3) == 0) {
                long long ro = z1 * sR1 + z2 * sR2;
                atomicAdd(rowsum + ro + r0, s0);
                atomicAdd(rowsum + ro + r0 + 8, s1);
            }
        }
    } else if (MODE == 3) {
#pragma unroll
        for (int tm = 0; tm < 4; tm++) {
            const int r0 = m0 + wm * 64 + tm * 16 + (lane >> 2);
#pragma unroll
            for (int tn = 0; tn < 4; tn++) {
                const int col = n0 + wn * 32 + tn * 8 + (lane & 3) * 2;
                const float sc = (col < 512) ? 0.125f : 1.0f;
                float v0 = (c[tm][tn][0] + bias[col])     * sc;
                float v1 = (c[tm][tn][1] + bias[col + 1]) * sc;
                float v2 = (c[tm][tn][2] + bias[col])     * sc;
                float v3 = (c[tm][tn][3] + bias[col + 1]) * sc;
                __nv_bfloat16 h0 = __float2bfloat16(v0), h1 = __float2bfloat16(v1);
                __nv_bfloat16 h2 = __float2bfloat16(v2), h3 = __float2bfloat16(v3);
                __nv_bfloat16 l0 = __float2bfloat16(v0 - __bfloat162float(h0));
                __nv_bfloat16 l1 = __float2bfloat16(v1 - __bfloat162float(h1));
                __nv_bfloat16 l2 = __float2bfloat16(v2 - __bfloat162float(h2));
                __nv_bfloat16 l3 = __float2bfloat16(v3 - __bfloat162float(h3));
                long long o0 = zC + (long long)r0 * ldc + col;
                long long o1 = o0 + 8LL * ldc;
                *reinterpret_cast<uint32_t*>(Hout + o0) = pack_bf2(h0, h1);
                *reinterpret_cast<uint32_t*>(Lout + o0) = pack_bf2(l0, l1);
                *reinterpret_cast<uint32_t*>(Hout + o1) = pack_bf2(h2, h3);
                *reinterpret_cast<uint32_t*>(Lout + o1) = pack_bf2(l2, l3);
            }
        }
    } else {
#pragma unroll
        for (int tm = 0; tm < 4; tm++) {
            const int r0 = m0 + wm * 64 + tm * 16 + (lane >> 2);
#pragma unroll
            for (int tn = 0; tn < 4; tn++) {
                const int col = n0 + wn * 32 + tn * 8 + (lane & 3) * 2;
                float2 v0 = make_float2(c[tm][tn][0], c[tm][tn][1]);
                float2 v1 = make_float2(c[tm][tn][2], c[tm][tn][3]);
                if (MODE == 1) {
                    v0.x += bias[col]; v0.y += bias[col + 1];
                    v1.x += bias[col]; v1.y += bias[col + 1];
                }
                long long o0 = zC + (long long)r0 * ldc + col;
                *reinterpret_cast<float2*>(C + o0) = v0;
                *reinterpret_cast<float2*>(C + o0 + 8LL * ldc) = v1;
            }
        }
    }
}

// ---------------------------------------------------------------------------
// u-GEMM (fp16, 1-term): C[M,N] = A @ B^T with A = Ef [M,K] fp16 single plane,
// B = xTh fp16 [N,K] single plane. Per tm: ONE ldsm_x4, 4 MMAs.
// 2 smem planes (A, Bh); stage 20480B x 2. fp32 C out.
// ---------------------------------------------------------------------------
#define USTAGE_BYTES (2 * PLANE_BYTES)  // 20480

__global__ void __launch_bounds__(256, 2)
u_gemm(const __half* __restrict__ A, const __half* __restrict__ Bh16,
       float* __restrict__ C,
       int K, int lda, int ldb, int ldc, int zdiv,
       long long sA1, long long sA2, long long sB1, long long sB2,
       long long sC1, long long sC2)
{
    extern __shared__ __align__(16) char smem[];
    const uint32_t sb = smem_u32(smem);

    const int tid = threadIdx.x;
    const int lane = tid & 31, wid = tid >> 5;
    const int wm = wid & 1, wn = wid >> 1;
    const int m0 = blockIdx.y * 128, n0 = blockIdx.x * 128;
    const int z1 = blockIdx.z / zdiv, z2 = blockIdx.z % zdiv;
    A    += z1 * sA1 + z2 * sA2;
    Bh16 += z1 * sB1 + z2 * sB2;
    const long long zC = z1 * sC1 + z2 * sC2;

    // loader: planes 0=A, 1=Bh; 128 threads each (4 cp16 per thread)
    const int tsel = tid >> 7;                   // 0 or 1
    const __half* gbase = (tsel == 0) ? A : Bh16;
    const int row0 = (tsel == 0) ? m0 : n0;
    const int ld   = (tsel == 0) ? lda : ldb;
    const int r128 = tid & 127;
    const uint32_t plane_off = (uint32_t)tsel * PLANE_BYTES;

    const int nch = K >> 5;

#define ULOAD(buf, k0) do { \
    uint32_t st_ = sb + (buf) * USTAGE_BYTES + plane_off; \
    _Pragma("unroll") \
    for (int it_ = 0; it_ < 4; it_++) { \
        int idx_ = r128 + it_ * 128; \
        int row_ = idx_ >> 2, seg_ = idx_ & 3; \
        const __half* g_ = gbase + (long long)(row0 + row_) * ld + (k0) + seg_ * 8; \
        cp16(st_ + row_ * PITCH + seg_ * 16, g_); \
    } \
    CP_COMMIT(); \
} while (0)

    ULOAD(0, 0);

    float c[4][4][4];
#pragma unroll
    for (int a = 0; a < 4; a++)
#pragma unroll
        for (int b = 0; b < 4; b++)
#pragma unroll
            for (int q = 0; q < 4; q++) c[a][b][q] = 0.0f;

    for (int i = 0; i < nch; i++) {
        if (i + 1 < nch) {
            ULOAD((i + 1) & 1, (i + 1) * 32);
            CP_WAIT(1);
        } else {
            CP_WAIT(0);
        }
        __syncthreads();

        const uint32_t stg = sb + (i & 1) * USTAGE_BYTES;
        const uint32_t a_row_off = (uint32_t)(wm * 64 + (lane & 15)) * PITCH + (lane >> 4) * 16;
        const uint32_t b_row_off = (uint32_t)(wn * 32 + (lane & 7)) * PITCH + ((lane >> 3) & 1) * 16;

#pragma unroll
        for (int k16 = 0; k16 < 2; k16++) {
            const uint32_t ko = k16 * 32;
            uint32_t bh[4][2];
#pragma unroll
            for (int tn = 0; tn < 4; tn++)
                ldsm_x2(bh[tn], stg + 1 * PLANE_BYTES + tn * 8 * PITCH + b_row_off + ko);
#pragma unroll
            for (int tm = 0; tm < 4; tm++) {
                uint32_t ah[4];
                ldsm_x4(ah, stg + 0 * PLANE_BYTES + tm * 16 * PITCH + a_row_off + ko);
#pragma unroll
                for (int tn = 0; tn < 4; tn++)
                    mma16816h(c[tm][tn], ah, bh[tn]);
            }
        }
        __syncthreads();
    }
#undef ULOAD

#pragma unroll
    for (int tm = 0; tm < 4; tm++) {
        const int r0 = m0 + wm * 64 + tm * 16 + (lane >> 2);
#pragma unroll
        for (int tn = 0; tn < 4; tn++) {
            const int col = n0 + wn * 32 + tn * 8 + (lane & 3) * 2;
            long long o0 = zC + (long long)r0 * ldc + col;
            *reinterpret_cast<float2*>(C + o0) = make_float2(c[tm][tn][0], c[tm][tn][1]);
            *reinterpret_cast<float2*>(C + o0 + 8LL * ldc) = make_float2(c[tm][tn][2], c[tm][tn][3]);
        }
    }
}

// ---------------------------------------------------------------------------
// prep: bv@Wo partials (grid (2,64)) + lambda (block (0,0), warp 0)
// ---------------------------------------------------------------------------
__global__ void prep_kernel(const float* __restrict__ bv, const float* __restrict__ Wo,
                            const float* __restrict__ lq1, const float* __restrict__ lk1,
                            const float* __restrict__ lq2, const float* __restrict__ lk2)
{
    if (blockIdx.x == 0 && blockIdx.y == 0 && threadIdx.x < 32) {
        int t = threadIdx.x;
        float a = lq1[t] * lk1[t] + lq1[t + 32] * lk1[t + 32];
        float b = lq2[t] * lk2[t] + lq2[t + 32] * lk2[t + 32];
#pragma unroll
        for (int o = 16; o > 0; o >>= 1) {
            a += __shfl_down_sync(0xFFFFFFFFu, a, o);
            b += __shfl_down_sync(0xFFFFFFFFu, b, o);
        }
        if (t == 0)
            g_lam = expf(a) - expf(b) + (0.8f - 0.6f);
    }
    int j  = blockIdx.x * 256 + threadIdx.x;   // 0..511
    int k0 = blockIdx.y * 128;
    float s = 0.0f;
#pragma unroll 4
    for (int k = k0; k < k0 + 128; k++)
        s = fmaf(bv[k], Wo[(long long)k * 512 + j], s);
    g_bfp[blockIdx.y * 512 + j] = s;
}

// ---------------------------------------------------------------------------
// x -> {xh,xl} bf16 (row-major) AND xT16h fp16 (transposed per batch)
// ---------------------------------------------------------------------------
__global__ void conv_x_kernel(const float* __restrict__ x)
{
    __shared__ float tile[32][33];
    const int z = blockIdx.z;
    const int c0 = blockIdx.x * 32, r0 = blockIdx.y * 32;
    const int tx = threadIdx.x, ty = threadIdx.y;
    const float* src = x + (long long)z * 2048 * 512;
#pragma unroll
    for (int j = 0; j < 32; j += 8) {
        float v = src[(long long)(r0 + ty + j) * 512 + c0 + tx];
        tile[ty + j][tx] = v;
        long long o = ((long long)z * 2048 + r0 + ty + j) * 512 + c0 + tx;
        __nv_bfloat16 h = __float2bfloat16(v);
        g_xh[o] = h;
        g_xl[o] = __float2bfloat16(v - __bfloat162float(h));
    }
    __syncthreads();
#pragma unroll
    for (int j = 0; j < 32; j += 8) {
        float v = tile[tx][ty + j];
        long long o = (long long)z * 512 * 2048 + (long long)(c0 + ty + j) * 2048 + r0 + tx;
        g_xT16h[o] = __float2half(v);
    }
}

// transpose fp32 [R,C] -> bf16 hi/lo [C,R]
__global__ void conv_trans(const float* __restrict__ src,
                           __nv_bfloat16* __restrict__ dh, __nv_bfloat16* __restrict__ dl,
                           int R, int C)
{
    __shared__ float tile[32][33];
    int c0 = blockIdx.x * 32, r0 = blockIdx.y * 32;
    int tx = threadIdx.x, ty = threadIdx.y;
#pragma unroll
    for (int j = 0; j < 32; j += 8)
        tile[ty + j][tx] = src[(long long)(r0 + ty + j) * C + c0 + tx];
    __syncthreads();
#pragma unroll
    for (int j = 0; j < 32; j += 8) {
        float v = tile[tx][ty + j];
        long long o = (long long)(c0 + ty + j) * R + r0 + tx;
        __nv_bfloat16 h = __float2bfloat16(v);
        dh[o] = h;
        dl[o] = __float2bfloat16(v - __bfloat162float(h));
    }
}

// fp32 -> bf16 hi/lo
__global__ void conv_plain(const float* __restrict__ src,
                           __nv_bfloat16* __restrict__ hi, __nv_bfloat16* __restrict__ lo,
                           long long n)
{
    long long i = (long long)blockIdx.x * 256 + threadIdx.x;
    if (i >= n) return;
    float v = src[i];
    __nv_bfloat16 h = __float2bfloat16(v);
    hi[i] = h;
    lo[i] = __float2bfloat16(v - __bfloat162float(h));
}

// t = (1/S1) o u1 - (lam/S2) o u2  -> bf16 hi/lo  (1/16 scaling cancels)
__global__ void combine_kernel()
{
    long long i = (long long)blockIdx.x * 256 + threadIdx.x;   // over 4096*512
    int row = (int)(i >> 9);
    float c1 = 1.0f / g_S[row];
    float c2 = g_lam / g_S[4096 + row];
    float v = c1 * g_u[i] - c2 * g_u[i + 2097152];
    __nv_bfloat16 h = __float2bfloat16(v);
    g_th[i] = h;
    g_tl[i] = __float2bfloat16(v - __bfloat162float(h));
}

// reduce 8 split-K slabs of W2^T -> bf16 hi/lo; blocks 0-1 also build bfin
__global__ void w2_reduce_conv(const float* __restrict__ bo)
{
    int i = blockIdx.x * 256 + threadIdx.x;   // 0..262143
    float s = 0.0f;
#pragma unroll
    for (int z = 0; z < 8; z++) s += g_W2p[(long long)z * 262144 + i];
    __nv_bfloat16 h = __float2bfloat16(s);
    g_w2Th[i] = h;
    g_w2Tl[i] = __float2bfloat16(s - __bfloat162float(h));

    if (blockIdx.x < 2) {
        int j = i;  // 0..511
        float b = 0.0f;
#pragma unroll
        for (int z = 0; z < 64; z++) b += g_bfp[z * 512 + j];
        g_bfin[j] = fmaf(1.0f - g_lam, b, bo[j]);
    }
}

// ---------------------------------------------------------------------------
// Host orchestration
// ---------------------------------------------------------------------------
extern "C" void kernel_launch(void* const* d_in, const int* in_sizes, int n_in,
                              void* d_out, int out_size)
{
    const float* x    = (const float*)d_in[0];
    const float* Wqkv = (const float*)d_in[1];
    const float* bqkv = (const float*)d_in[2];
    const float* Wv   = (const float*)d_in[3];
    const float* bv   = (const float*)d_in[4];
    const float* Wo   = (const float*)d_in[5];
    const float* bo   = (const float*)d_in[6];
    const float* lq1  = (const float*)d_in[7];
    const float* lk1  = (const float*)d_in[8];
    const float* lq2  = (const float*)d_in[9];
    const float* lk2  = (const float*)d_in[10];
    float* out = (float*)d_out;

    const int SMEM  = 2 * STAGE_BYTES;    // 81920
    const int USMEM = 2 * USTAGE_BYTES;   // 40960
    cudaFuncSetAttribute(hmma_gemm<0>, cudaFuncAttributeMaxDynamicSharedMemorySize, SMEM);
    cudaFuncSetAttribute(hmma_gemm<1>, cudaFuncAttributeMaxDynamicSharedMemorySize, SMEM);
    cudaFuncSetAttribute(hmma_gemm<2>, cudaFuncAttributeMaxDynamicSharedMemorySize, SMEM);
    cudaFuncSetAttribute(hmma_gemm<3>, cudaFuncAttributeMaxDynamicSharedMemorySize, SMEM);
    cudaFuncSetAttribute(u_gemm, cudaFuncAttributeMaxDynamicSharedMemorySize, USMEM);

#define SYM(v, s) cudaGetSymbolAddress((void**)&v, s)
    float *W2p, *S, *u, *bfin;
    __nv_bfloat16 *qkvh, *qkvl, *xh, *xl, *wqTh, *wqTl;
    __nv_bfloat16 *woTh, *woTl, *wvh, *wvl, *th, *tl, *w2Th, *w2Tl;
    __half *Ef, *xT16h;
    SYM(W2p, g_W2p); SYM(S, g_S); SYM(u, g_u); SYM(bfin, g_bfin);
    SYM(qkvh, g_qkvh); SYM(qkvl, g_qkvl); SYM(xh, g_xh); SYM(xl, g_xl);
    SYM(xT16h, g_xT16h); SYM(wqTh, g_wqTh); SYM(wqTl, g_wqTl);
    SYM(woTh, g_woTh); SYM(woTl, g_woTl); SYM(wvh, g_wvh); SYM(wvl, g_wvl);
    SYM(Ef, g_Ef); SYM(th, g_th); SYM(tl, g_tl);
    SYM(w2Th, g_w2Th); SYM(w2Tl, g_w2Tl);
#undef SYM

    const long long PS = 2048LL * 2048;

    // (0) x -> bf16 planes + fp16 transposed plane
    conv_x_kernel<<<dim3(16, 64, 2), dim3(32, 8)>>>(x);
    // (1) Wqkv^T -> bf16 hi/lo
    conv_trans<<<dim3(32, 16, 1), dim3(32, 8)>>>(Wqkv, wqTh, wqTl, 512, 1024);
    // (2) qkv GEMM: bf16 hi/lo epilogue with bias + Q-scale; zeroes g_S
    hmma_gemm<3><<<dim3(8, 32, 1), 256, SMEM>>>(xh, xl, wqTh, wqTl,
        nullptr, bqkv, qkvh, qkvl, nullptr, 512, 512, 512, 1024, 1,
        0, 0, 0, 0, 0, 0, 0, 0);
    // (3) E = exp(Q K^T)/16 fp16 plane + rowsums/16; z = map*2 + batch  [PROFILED]
    hmma_gemm<2><<<dim3(16, 16, 4), 256, SMEM>>>(qkvh, qkvl, qkvh + 512, qkvl + 512,
        nullptr, nullptr, (__nv_bfloat16*)Ef, nullptr, S, 256, 1024, 1024, 2048, 2,
        256, 2048LL * 1024, 256, 2048LL * 1024, 2 * PS, PS, 4096, 2048);
    // (4) prep: lambda + bv@Wo partials
    prep_kernel<<<dim3(2, 64), 256>>>(bv, Wo, lq1, lk1, lq2, lk2);
    // (5) u = Ef @ xh16 (fp16, 1-term); z = map*2 + batch
    u_gemm<<<dim3(4, 16, 4), 256, USMEM>>>(Ef, xT16h, u,
        2048, 2048, 2048, 512, 2,
        2 * PS, PS, 0, 512LL * 2048, 2LL * 2048 * 512, 2048LL * 512);
    // (6) t = c1 o u1 - c2 o u2 -> bf16 hi/lo
    combine_kernel<<<(4096 * 512) / 256, 256>>>();
    // (7,8) Wo^T, Wv -> bf16 hi/lo
    conv_trans<<<dim3(16, 256, 1), dim3(32, 8)>>>(Wo, woTh, woTl, 8192, 512);
    conv_plain<<<(512 * 8192) / 256, 256>>>(Wv, wvh, wvl, 512LL * 8192);
    // (9) W2^T = Wo^T @ Wv^T, split-K x8
    hmma_gemm<0><<<dim3(4, 4, 8), 256, SMEM>>>(woTh, woTl, wvh, wvl, W2p,
        nullptr, nullptr, nullptr, nullptr, 1024, 8192, 8192, 512, 1,
        1024, 0, 1024, 0, 262144, 0, 0, 0);
    // (10) reduce W2 slabs -> bf16 hi/lo; also bfin = (1-lam)*(bv@Wo)+bo
    w2_reduce_conv<<<1024, 256>>>(bo);
    // (11) out = t @ W2 + bfin
    hmma_gemm<1><<<dim3(4, 32, 1), 256, SMEM>>>(th, tl, w2Th, w2Tl, out, bfin,
        nullptr, nullptr, nullptr, 512, 512, 512, 512, 1,
        0, 0, 0, 0, 0, 0, 0, 0);
}